// round 1
// baseline (speedup 1.0000x reference)
#include <cuda_runtime.h>
#include <cstdint>

#define TT 8192
#define DD 2048

typedef unsigned long long ull;

// ---------------- device scratch (no allocations allowed) ----------------
__device__ float g_pre[(size_t)TT * DD];   // 64 MB: pre = x @ W1^T + b1
__device__ float g_h[2][DD];               // ping-pong h buffers
__device__ unsigned g_count;               // barrier arrive counter (returns to 0)
__device__ volatile unsigned g_gen;        // barrier generation (monotonic)

// ---------------- packed f32x2 helpers ----------------
__device__ __forceinline__ ull pk(float lo, float hi) {
    ull r;
    asm("mov.b64 %0, {%1, %2};" : "=l"(r) : "f"(lo), "f"(hi));
    return r;
}
__device__ __forceinline__ void upk(ull v, float& lo, float& hi) {
    asm("mov.b64 {%0, %1}, %2;" : "=f"(lo), "=f"(hi) : "l"(v));
}
__device__ __forceinline__ void fma2(ull& d, ull a, ull b) {
    asm("fma.rn.f32x2 %0, %1, %2, %0;" : "+l"(d) : "l"(a), "l"(b));
}

// ---------------- GEMM: g_pre[t][n] = sum_k x[t][k] * W1[n][k] + b1[n] ----------------
#define BM 128
#define BN 128
#define BK 16
#define LDP 132   // padded row to cut STS bank conflicts, keeps 16B alignment

__global__ __launch_bounds__(256, 2) void gemm_kernel(
    const float* __restrict__ A,      // x  (TT x DD), row-major
    const float* __restrict__ B,      // W1 (DD x DD), row-major (we compute A @ B^T)
    const float* __restrict__ bias)   // b1
{
    __shared__ __align__(16) float As[BK][LDP];
    __shared__ __align__(16) float Bs[BK][LDP];

    const int tid = threadIdx.x;
    const int m0 = blockIdx.y * BM;
    const int n0 = blockIdx.x * BN;
    const int tx = tid & 15;          // 16 col-threads
    const int ty = tid >> 4;          // 16 row-threads

    ull acc[8][4];
#pragma unroll
    for (int r = 0; r < 8; r++)
#pragma unroll
        for (int c = 0; c < 4; c++) acc[r][c] = 0ull;

    for (int k0 = 0; k0 < DD; k0 += BK) {
        // load 128x16 tiles of A and B (transposed into [k][m]/[k][n])
#pragma unroll
        for (int i = 0; i < 2; i++) {
            int id = tid + i * 256;
            int r = id >> 2;
            int c = (id & 3) * 4;
            float4 va = *(const float4*)(A + (size_t)(m0 + r) * DD + k0 + c);
            As[c + 0][r] = va.x; As[c + 1][r] = va.y;
            As[c + 2][r] = va.z; As[c + 3][r] = va.w;
            float4 vb = *(const float4*)(B + (size_t)(n0 + r) * DD + k0 + c);
            Bs[c + 0][r] = vb.x; Bs[c + 1][r] = vb.y;
            Bs[c + 2][r] = vb.z; Bs[c + 3][r] = vb.w;
        }
        __syncthreads();

#pragma unroll
        for (int k = 0; k < BK; k++) {
            float4 a0 = *(const float4*)&As[k][ty * 8];
            float4 a1 = *(const float4*)&As[k][ty * 8 + 4];
            ulonglong2 bq0 = *(const ulonglong2*)&Bs[k][tx * 8];
            ulonglong2 bq1 = *(const ulonglong2*)&Bs[k][tx * 8 + 4];
            ull bp0 = bq0.x, bp1 = bq0.y, bp2 = bq1.x, bp3 = bq1.y;
            float ar[8] = {a0.x, a0.y, a0.z, a0.w, a1.x, a1.y, a1.z, a1.w};
#pragma unroll
            for (int r = 0; r < 8; r++) {
                ull ad = pk(ar[r], ar[r]);
                fma2(acc[r][0], ad, bp0);
                fma2(acc[r][1], ad, bp1);
                fma2(acc[r][2], ad, bp2);
                fma2(acc[r][3], ad, bp3);
            }
        }
        __syncthreads();
    }

    // epilogue: add bias, store to g_pre
#pragma unroll
    for (int c = 0; c < 4; c++) {
        int n = n0 + tx * 8 + c * 2;
        float blo = bias[n], bhi = bias[n + 1];
#pragma unroll
        for (int r = 0; r < 8; r++) {
            float lo, hi;
            upk(acc[r][c], lo, hi);
            int m = m0 + ty * 8 + r;
            *(float2*)(g_pre + (size_t)m * DD + n) = make_float2(lo + blo, hi + bhi);
        }
    }
}

// ---------------- persistent scan kernel ----------------
#define NCTA 128
#define NTH  512
#define ROWS 16   // DD / NCTA
// thread t owns k-chunk [4t, 4t+4); warp w reduces row w of this CTA's block

__device__ __forceinline__ void grid_barrier(unsigned& genl) {
    __syncthreads();
    if (threadIdx.x == 0) {
        __threadfence();
        unsigned a = atomicAdd(&g_count, 1u);
        if (a == (unsigned)NCTA - 1u) {
            g_count = 0u;          // nobody touches count until gen flips
            __threadfence();
            g_gen = genl + 1u;     // release
        } else {
            while (g_gen != genl + 1u) { }
            __threadfence();       // acquire
        }
    }
    genl += 1u;
    __syncthreads();
}

__global__ __launch_bounds__(NTH, 1) void scan_kernel(
    const float* __restrict__ h0,
    const float* __restrict__ W2,
    const float* __restrict__ b2)
{
    __shared__ __align__(16) float s_part[ROWS][NTH];   // 32 KB partials
    const int tid  = threadIdx.x;
    const int blk  = blockIdx.x;
    const int lane = tid & 31;
    const int wid  = tid >> 5;
    const int k0   = tid * 4;

    unsigned genl = g_gen;   // all CTAs read the same launch-start value

    // register-resident W2 slab: rows [blk*16, blk*16+16), cols [k0, k0+4)
    ull w2r[ROWS][2];
#pragma unroll
    for (int j = 0; j < ROWS; j++) {
        float4 w = *(const float4*)(W2 + (size_t)(blk * ROWS + j) * DD + k0);
        w2r[j][0] = pk(w.x, w.y);
        w2r[j][1] = pk(w.z, w.w);
    }
    const int myrow = blk * ROWS + wid;
    const float myb2 = b2[myrow];
    float pre_next = __ldg(&g_pre[(size_t)0 * DD + myrow]);   // prefetch pre for t=0

    // seed h buffer 0 with h0
    int g = blk * NTH + tid;
    if (g < DD) g_h[0][g] = h0[g];
    grid_barrier(genl);

    for (int t = 0; t < TT; t++) {
        // fresh (L1-bypassing) read of h_{t-1}
        float4 hv = __ldcv((const float4*)(g_h[t & 1] + k0));
        float pre_cur = pre_next;
        if (t + 1 < TT) pre_next = __ldg(&g_pre[(size_t)(t + 1) * DD + myrow]);

        ull h01 = pk(hv.x, hv.y);
        ull h23 = pk(hv.z, hv.w);
#pragma unroll
        for (int j = 0; j < ROWS; j++) {
            ull a = 0ull;
            fma2(a, w2r[j][0], h01);
            fma2(a, w2r[j][1], h23);
            float lo, hi;
            upk(a, lo, hi);
            s_part[j][tid] = lo + hi;
        }
        __syncthreads();

        // warp `wid` reduces row `wid`: 512 partials -> 1 value
        const float* rowp = s_part[wid];
        float s = 0.f;
#pragma unroll
        for (int i = 0; i < 4; i++) {
            float4 v = *(const float4*)(rowp + i * 128 + lane * 4);
            s += (v.x + v.y) + (v.z + v.w);
        }
        s += __shfl_xor_sync(0xffffffffu, s, 16);
        s += __shfl_xor_sync(0xffffffffu, s, 8);
        s += __shfl_xor_sync(0xffffffffu, s, 4);
        s += __shfl_xor_sync(0xffffffffu, s, 2);
        s += __shfl_xor_sync(0xffffffffu, s, 1);

        if (lane == 0) {
            float y = s + pre_cur + myb2;
            g_h[(t + 1) & 1][myrow] = fmaxf(y, 0.f);
            __threadfence();
        }
        grid_barrier(genl);   // includes the __syncthreads protecting s_part reuse
    }
    // final h lives in g_h[0]  (TT even: step TT-1 writes buffer (TT)&1 = 0)
}

// ---------------- final tiny matvec: out[j] = h . Wf[j] + bf[j] ----------------
__global__ void final_kernel(const float* __restrict__ Wf,
                             const float* __restrict__ bf,
                             float* __restrict__ out)
{
    const int wid = threadIdx.x >> 5;   // 4 warps, one per output row
    const int lane = threadIdx.x & 31;
    const float* h = g_h[0];
    const float* w = Wf + (size_t)wid * DD;
    float s = 0.f;
#pragma unroll
    for (int i = 0; i < 16; i++) {
        int k = i * 128 + lane * 4;
        float4 hv = *(const float4*)(h + k);
        float4 wv = *(const float4*)(w + k);
        s += hv.x * wv.x + hv.y * wv.y + hv.z * wv.z + hv.w * wv.w;
    }
    for (int off = 16; off; off >>= 1) s += __shfl_xor_sync(0xffffffffu, s, off);
    if (lane == 0) out[wid] = s + bf[wid];
}

// ---------------- launch ----------------
extern "C" void kernel_launch(void* const* d_in, const int* in_sizes, int n_in,
                              void* d_out, int out_size)
{
    const float* x  = (const float*)d_in[0];
    const float* h0 = (const float*)d_in[1];
    const float* W1 = (const float*)d_in[2];
    const float* b1 = (const float*)d_in[3];
    const float* W2 = (const float*)d_in[4];
    const float* b2 = (const float*)d_in[5];
    const float* Wf = (const float*)d_in[6];
    const float* bf = (const float*)d_in[7];
    float* out = (float*)d_out;

    gemm_kernel<<<dim3(DD / BN, TT / BM), 256>>>(x, W1, b1);
    scan_kernel<<<NCTA, NTH>>>(h0, W2, b2);
    final_kernel<<<1, 128>>>(Wf, bf, out);
}

// round 5
// speedup vs baseline: 1.0905x; 1.0905x over previous
#include <cuda_runtime.h>
#include <cstdint>

#define TT 8192
#define DD 2048

typedef unsigned long long ull;

// ---------------- device scratch (no allocations allowed) ----------------
__device__ float g_pre[(size_t)TT * DD];        // 64 MB: pre = x @ W1^T + b1
__device__ ull   g_hs[(size_t)(TT + 1) * DD];   // 134 MB: {f32 value(lo), u32 tag(hi)} per h element

// ---------------- packed f32x2 helpers ----------------
__device__ __forceinline__ ull pk(float lo, float hi) {
    ull r;
    asm("mov.b64 %0, {%1, %2};" : "=l"(r) : "f"(lo), "f"(hi));
    return r;
}
__device__ __forceinline__ void upk(ull v, float& lo, float& hi) {
    asm("mov.b64 {%0, %1}, %2;" : "=f"(lo), "=f"(hi) : "l"(v));
}
__device__ __forceinline__ void fma2(ull& d, ull a, ull b) {
    asm("fma.rn.f32x2 %0, %1, %2, %0;" : "+l"(d) : "l"(a), "l"(b));
}
__device__ __forceinline__ ull add2(ull a, ull b) {
    ull r;
    asm("add.rn.f32x2 %0, %1, %2;" : "=l"(r) : "l"(a), "l"(b));
    return r;
}

// ---------------- volatile (morally-strong) 64-bit ld/st: guaranteed visibility ----
__device__ __forceinline__ ull ldvol_u64(const ull* p) {
    ull v;
    asm volatile("ld.volatile.global.u64 %0, [%1];" : "=l"(v) : "l"(p));
    return v;
}
__device__ __forceinline__ void stvol_u64(ull* p, ull v) {
    asm volatile("st.volatile.global.u64 [%0], %1;" :: "l"(p), "l"(v));
}

// ---------------- poison kernel: clear all ready-tags ----------------
__global__ void poison_kernel() {
    uint4 z = make_uint4(0u, 0u, 0u, 0u);
    size_t n = (size_t)(TT + 1) * DD / 2;   // uint4 = 2 tagged elements
    uint4* dst = (uint4*)g_hs;
    for (size_t i = (size_t)blockIdx.x * blockDim.x + threadIdx.x; i < n;
         i += (size_t)gridDim.x * blockDim.x)
        dst[i] = z;
}

// ---------------- GEMM: g_pre[t][n] = sum_k x[t][k] * W1[n][k] + b1[n] ----------------
#define BM 128
#define BN 128
#define BK 16
#define LDP 132

__global__ __launch_bounds__(256, 2) void gemm_kernel(
    const float* __restrict__ A,      // x  (TT x DD)
    const float* __restrict__ B,      // W1 (DD x DD), computing A @ B^T
    const float* __restrict__ bias)   // b1
{
    __shared__ __align__(16) float As[BK][LDP];
    __shared__ __align__(16) float Bs[BK][LDP];

    const int tid = threadIdx.x;
    const int m0 = blockIdx.y * BM;
    const int n0 = blockIdx.x * BN;
    const int tx = tid & 15;
    const int ty = tid >> 4;

    ull acc[8][4];
#pragma unroll
    for (int r = 0; r < 8; r++)
#pragma unroll
        for (int c = 0; c < 4; c++) acc[r][c] = 0ull;

    for (int k0 = 0; k0 < DD; k0 += BK) {
#pragma unroll
        for (int i = 0; i < 2; i++) {
            int id = tid + i * 256;
            int r = id >> 2;
            int c = (id & 3) * 4;
            float4 va = *(const float4*)(A + (size_t)(m0 + r) * DD + k0 + c);
            As[c + 0][r] = va.x; As[c + 1][r] = va.y;
            As[c + 2][r] = va.z; As[c + 3][r] = va.w;
            float4 vb = *(const float4*)(B + (size_t)(n0 + r) * DD + k0 + c);
            Bs[c + 0][r] = vb.x; Bs[c + 1][r] = vb.y;
            Bs[c + 2][r] = vb.z; Bs[c + 3][r] = vb.w;
        }
        __syncthreads();

#pragma unroll
        for (int k = 0; k < BK; k++) {
            float4 a0 = *(const float4*)&As[k][ty * 8];
            float4 a1 = *(const float4*)&As[k][ty * 8 + 4];
            ulonglong2 bq0 = *(const ulonglong2*)&Bs[k][tx * 8];
            ulonglong2 bq1 = *(const ulonglong2*)&Bs[k][tx * 8 + 4];
            ull bp0 = bq0.x, bp1 = bq0.y, bp2 = bq1.x, bp3 = bq1.y;
            float ar[8] = {a0.x, a0.y, a0.z, a0.w, a1.x, a1.y, a1.z, a1.w};
#pragma unroll
            for (int r = 0; r < 8; r++) {
                ull ad = pk(ar[r], ar[r]);
                fma2(acc[r][0], ad, bp0);
                fma2(acc[r][1], ad, bp1);
                fma2(acc[r][2], ad, bp2);
                fma2(acc[r][3], ad, bp3);
            }
        }
        __syncthreads();
    }

#pragma unroll
    for (int c = 0; c < 4; c++) {
        int n = n0 + tx * 8 + c * 2;
        float blo = bias[n], bhi = bias[n + 1];
#pragma unroll
        for (int r = 0; r < 8; r++) {
            float lo, hi;
            upk(acc[r][c], lo, hi);
            int m = m0 + ty * 8 + r;
            *(float2*)(g_pre + (size_t)m * DD + n) = make_float2(lo + blo, hi + bhi);
        }
    }
}

// ---------------- persistent scan kernel (dataflow-synced via tagged words) --------
#define NCTA 128
#define NTH  512
#define ROWS 16   // DD / NCTA rows per CTA; warp w reduces row w
// thread t owns k-chunk [4t, 4t+4)

__global__ __launch_bounds__(NTH, 1) void scan_kernel(
    const float* __restrict__ h0,
    const float* __restrict__ W2,
    const float* __restrict__ b2)
{
    extern __shared__ ull s_part[];   // [ROWS][NTH] packed f32x2 partials (64 KB)
    const int tid  = threadIdx.x;
    const int blk  = blockIdx.x;
    const int lane = tid & 31;
    const int wid  = tid >> 5;
    const int k0   = tid * 4;

    // register-resident W2 slab: rows [blk*16, blk*16+16), cols [k0, k0+4)
    ull w2r[ROWS][2];
#pragma unroll
    for (int j = 0; j < ROWS; j++) {
        float4 w = *(const float4*)(W2 + (size_t)(blk * ROWS + j) * DD + k0);
        w2r[j][0] = pk(w.x, w.y);
        w2r[j][1] = pk(w.z, w.w);
    }
    const int myrow = blk * ROWS + wid;
    const float myb2 = b2[myrow];
    float pre_next = __ldg(&g_pre[myrow]);   // pre for t=0

    // seed h[0]: one tagged volatile ST.64 per row
    if (lane == 0) {
        float v = __ldg(&h0[myrow]);
        stvol_u64(&g_hs[myrow], ((ull)1 << 32) | (ull)__float_as_uint(v));
    }

    for (int t = 0; t < TT; t++) {
        // dataflow wait: volatile 64-bit polls (guaranteed fresh + live)
        const ull* src = g_hs + (size_t)t * DD + k0;
        ull e0 = ldvol_u64(src + 0);
        ull e1 = ldvol_u64(src + 1);
        ull e2 = ldvol_u64(src + 2);
        ull e3 = ldvol_u64(src + 3);
        while ((unsigned)((e0 & e1 & e2 & e3) >> 32) == 0u) {
            e0 = ldvol_u64(src + 0);
            e1 = ldvol_u64(src + 1);
            e2 = ldvol_u64(src + 2);
            e3 = ldvol_u64(src + 3);
        }
        float h0v = __uint_as_float((unsigned)e0);
        float h1v = __uint_as_float((unsigned)e1);
        float h2v = __uint_as_float((unsigned)e2);
        float h3v = __uint_as_float((unsigned)e3);

        float pre_cur = pre_next;
        if (t + 1 < TT) pre_next = __ldg(&g_pre[(size_t)(t + 1) * DD + myrow]);

        ull h01 = pk(h0v, h1v);
        ull h23 = pk(h2v, h3v);
#pragma unroll
        for (int j = 0; j < ROWS; j++) {
            ull acc = 0ull;
            fma2(acc, w2r[j][0], h01);
            fma2(acc, w2r[j][1], h23);
            s_part[j * NTH + tid] = acc;     // keep packed; reducer folds lo+hi
        }
        __syncthreads();

        // warp `wid` reduces row `wid`: 512 packed partials -> 1 scalar
        const ull* rowp = s_part + wid * NTH;
        ull v[16];
#pragma unroll
        for (int i = 0; i < 16; i++) v[i] = rowp[i * 32 + lane];
#pragma unroll
        for (int stride = 8; stride >= 1; stride >>= 1)
#pragma unroll
            for (int i = 0; i < stride; i++) v[i] = add2(v[i], v[i + stride]);
        float lo, hi;
        upk(v[0], lo, hi);
        float s = lo + hi;
        s += __shfl_xor_sync(0xffffffffu, s, 16);
        s += __shfl_xor_sync(0xffffffffu, s, 8);
        s += __shfl_xor_sync(0xffffffffu, s, 4);
        s += __shfl_xor_sync(0xffffffffu, s, 2);
        s += __shfl_xor_sync(0xffffffffu, s, 1);

        if (lane == 0) {
            float y = fmaxf(s + pre_cur + myb2, 0.f);
            stvol_u64(&g_hs[(size_t)(t + 1) * DD + myrow],
                      ((ull)1 << 32) | (ull)__float_as_uint(y));
        }
        __syncthreads();   // protect s_part reuse next iteration
    }
}

// ---------------- final tiny matvec: out[j] = h . Wf[j] + bf[j] ----------------
__global__ void final_kernel(const float* __restrict__ Wf,
                             const float* __restrict__ bf,
                             float* __restrict__ out)
{
    const int wid = threadIdx.x >> 5;   // 4 warps, one per output row
    const int lane = threadIdx.x & 31;
    const ull* h = g_hs + (size_t)TT * DD;
    const float* w = Wf + (size_t)wid * DD;
    float s = 0.f;
#pragma unroll
    for (int i = 0; i < 16; i++) {
        int k = i * 128 + lane * 4;
        float4 wv = *(const float4*)(w + k);
        float v0, v1, v2, v3, dummy;
        upk(h[k + 0], v0, dummy);
        upk(h[k + 1], v1, dummy);
        upk(h[k + 2], v2, dummy);
        upk(h[k + 3], v3, dummy);
        s += v0 * wv.x + v1 * wv.y + v2 * wv.z + v3 * wv.w;
    }
    for (int off = 16; off; off >>= 1) s += __shfl_xor_sync(0xffffffffu, s, off);
    if (lane == 0) out[wid] = s + bf[wid];
}

// ---------------- launch ----------------
extern "C" void kernel_launch(void* const* d_in, const int* in_sizes, int n_in,
                              void* d_out, int out_size)
{
    const float* x  = (const float*)d_in[0];
    const float* h0 = (const float*)d_in[1];
    const float* W1 = (const float*)d_in[2];
    const float* b1 = (const float*)d_in[3];
    const float* W2 = (const float*)d_in[4];
    const float* b2 = (const float*)d_in[5];
    const float* Wf = (const float*)d_in[6];
    const float* bf = (const float*)d_in[7];
    float* out = (float*)d_out;

    cudaFuncSetAttribute(scan_kernel, cudaFuncAttributeMaxDynamicSharedMemorySize,
                         ROWS * NTH * (int)sizeof(ull));

    poison_kernel<<<2048, 256>>>();
    gemm_kernel<<<dim3(DD / BN, TT / BM), 256>>>(x, W1, b1);
    scan_kernel<<<NCTA, NTH, ROWS * NTH * sizeof(ull)>>>(h0, W2, b2);
    final_kernel<<<1, 128>>>(Wf, bf, out);
}

// round 6
// speedup vs baseline: 1.4200x; 1.3021x over previous
#include <cuda_runtime.h>
#include <cstdint>

#define TT 8192
#define DD 2048

typedef unsigned long long ull;

// ---------------- device scratch (no allocations allowed) ----------------
__device__ float g_pre[(size_t)TT * DD];        // 64 MB: pre = x @ W1^T + b1
__device__ float g_hs[(size_t)(TT + 1) * DD];   // 64 MB: h per step; sign bit = not-ready

// ---------------- packed f32x2 helpers ----------------
__device__ __forceinline__ ull pk(float lo, float hi) {
    ull r;
    asm("mov.b64 %0, {%1, %2};" : "=l"(r) : "f"(lo), "f"(hi));
    return r;
}
__device__ __forceinline__ void upk(ull v, float& lo, float& hi) {
    asm("mov.b64 {%0, %1}, %2;" : "=f"(lo), "=f"(hi) : "l"(v));
}
__device__ __forceinline__ void fma2(ull& d, ull a, ull b) {
    asm("fma.rn.f32x2 %0, %1, %2, %0;" : "+l"(d) : "l"(a), "l"(b));
}
__device__ __forceinline__ ull add2(ull a, ull b) {
    ull r;
    asm("add.rn.f32x2 %0, %1, %2;" : "=l"(r) : "l"(a), "l"(b));
    return r;
}

// ---------------- volatile ld/st (morally strong, guaranteed fresh+live) ----------
__device__ __forceinline__ uint4 ldvol_v4(const float* p) {
    uint4 v;
    asm volatile("ld.volatile.global.v4.u32 {%0,%1,%2,%3}, [%4];"
                 : "=r"(v.x), "=r"(v.y), "=r"(v.z), "=r"(v.w) : "l"(p));
    return v;
}
__device__ __forceinline__ void stvol_f32(float* p, float v) {
    asm volatile("st.volatile.global.f32 [%0], %1;" :: "l"(p), "f"(v));
}

// ---------------- poison kernel: set sign bits (= not ready) everywhere ----------
__global__ void poison_kernel() {
    uint4 p = make_uint4(0xFFFFFFFFu, 0xFFFFFFFFu, 0xFFFFFFFFu, 0xFFFFFFFFu);
    size_t n = (size_t)(TT + 1) * DD / 4;
    uint4* dst = (uint4*)g_hs;
    for (size_t i = (size_t)blockIdx.x * blockDim.x + threadIdx.x; i < n;
         i += (size_t)gridDim.x * blockDim.x)
        dst[i] = p;
}

// ---------------- GEMM: g_pre[t][n] = sum_k x[t][k] * W1[n][k] + b1[n] ----------------
#define BM 128
#define BN 128
#define BK 16
#define LDP 132

__global__ __launch_bounds__(256, 2) void gemm_kernel(
    const float* __restrict__ A,      // x  (TT x DD)
    const float* __restrict__ B,      // W1 (DD x DD), computing A @ B^T
    const float* __restrict__ bias)   // b1
{
    __shared__ __align__(16) float As[BK][LDP];
    __shared__ __align__(16) float Bs[BK][LDP];

    const int tid = threadIdx.x;
    const int m0 = blockIdx.y * BM;
    const int n0 = blockIdx.x * BN;
    const int tx = tid & 15;
    const int ty = tid >> 4;

    ull acc[8][4];
#pragma unroll
    for (int r = 0; r < 8; r++)
#pragma unroll
        for (int c = 0; c < 4; c++) acc[r][c] = 0ull;

    for (int k0 = 0; k0 < DD; k0 += BK) {
#pragma unroll
        for (int i = 0; i < 2; i++) {
            int id = tid + i * 256;
            int r = id >> 2;
            int c = (id & 3) * 4;
            float4 va = *(const float4*)(A + (size_t)(m0 + r) * DD + k0 + c);
            As[c + 0][r] = va.x; As[c + 1][r] = va.y;
            As[c + 2][r] = va.z; As[c + 3][r] = va.w;
            float4 vb = *(const float4*)(B + (size_t)(n0 + r) * DD + k0 + c);
            Bs[c + 0][r] = vb.x; Bs[c + 1][r] = vb.y;
            Bs[c + 2][r] = vb.z; Bs[c + 3][r] = vb.w;
        }
        __syncthreads();

#pragma unroll
        for (int k = 0; k < BK; k++) {
            float4 a0 = *(const float4*)&As[k][ty * 8];
            float4 a1 = *(const float4*)&As[k][ty * 8 + 4];
            ulonglong2 bq0 = *(const ulonglong2*)&Bs[k][tx * 8];
            ulonglong2 bq1 = *(const ulonglong2*)&Bs[k][tx * 8 + 4];
            ull bp0 = bq0.x, bp1 = bq0.y, bp2 = bq1.x, bp3 = bq1.y;
            float ar[8] = {a0.x, a0.y, a0.z, a0.w, a1.x, a1.y, a1.z, a1.w};
#pragma unroll
            for (int r = 0; r < 8; r++) {
                ull ad = pk(ar[r], ar[r]);
                fma2(acc[r][0], ad, bp0);
                fma2(acc[r][1], ad, bp1);
                fma2(acc[r][2], ad, bp2);
                fma2(acc[r][3], ad, bp3);
            }
        }
        __syncthreads();
    }

#pragma unroll
    for (int c = 0; c < 4; c++) {
        int n = n0 + tx * 8 + c * 2;
        float blo = bias[n], bhi = bias[n + 1];
#pragma unroll
        for (int r = 0; r < 8; r++) {
            float lo, hi;
            upk(acc[r][c], lo, hi);
            int m = m0 + ty * 8 + r;
            *(float2*)(g_pre + (size_t)m * DD + n) = make_float2(lo + blo, hi + bhi);
        }
    }
}

// ---------------- persistent scan kernel (sign-bit dataflow sync) ------------------
#define NCTA 128
#define NTH  512
#define ROWS 16   // DD / NCTA rows per CTA; warp w reduces row w
// thread t owns k-chunk [4t, 4t+4)

__global__ __launch_bounds__(NTH, 1) void scan_kernel(
    const float* __restrict__ h0,
    const float* __restrict__ W2,
    const float* __restrict__ b2)
{
    extern __shared__ ull s_part[];   // [ROWS][NTH] packed f32x2 partials (64 KB)
    const int tid  = threadIdx.x;
    const int blk  = blockIdx.x;
    const int lane = tid & 31;
    const int wid  = tid >> 5;
    const int k0   = tid * 4;

    // register-resident W2 slab: rows [blk*16, blk*16+16), cols [k0, k0+4)
    ull w2r[ROWS][2];
#pragma unroll
    for (int j = 0; j < ROWS; j++) {
        float4 w = *(const float4*)(W2 + (size_t)(blk * ROWS + j) * DD + k0);
        w2r[j][0] = pk(w.x, w.y);
        w2r[j][1] = pk(w.z, w.w);
    }
    const int myrow = blk * ROWS + wid;
    const float myb2 = b2[myrow];
    float pre_next = __ldg(&g_pre[myrow]);   // pre for t=0

    for (int t = 0; t < TT; t++) {
        float h0v, h1v, h2v, h3v;
        if (t == 0) {
            // h0 is kernel input: ready by definition, no polling (and may be negative)
            float4 hv = *(const float4*)(h0 + k0);
            h0v = hv.x; h1v = hv.y; h2v = hv.z; h3v = hv.w;
        } else {
            // one 16B volatile poll; sign bits are the ready flags
            const float* src = g_hs + (size_t)t * DD + k0;
            uint4 a = ldvol_v4(src);
            while (((a.x | a.y | a.z | a.w) & 0x80000000u) != 0u)
                a = ldvol_v4(src);
            h0v = __uint_as_float(a.x);
            h1v = __uint_as_float(a.y);
            h2v = __uint_as_float(a.z);
            h3v = __uint_as_float(a.w);
        }

        float pre_cur = pre_next;
        if (t + 1 < TT) pre_next = __ldg(&g_pre[(size_t)(t + 1) * DD + myrow]);

        ull h01 = pk(h0v, h1v);
        ull h23 = pk(h2v, h3v);
#pragma unroll
        for (int j = 0; j < ROWS; j++) {
            ull acc = 0ull;
            fma2(acc, w2r[j][0], h01);
            fma2(acc, w2r[j][1], h23);
            s_part[j * NTH + tid] = acc;     // keep packed; reducer folds lo+hi
        }
        __syncthreads();

        // warp `wid` reduces row `wid`: 512 packed partials -> 1 scalar
        const ull* rowp = s_part + wid * NTH;
        ull v[16];
#pragma unroll
        for (int i = 0; i < 16; i++) v[i] = rowp[i * 32 + lane];
#pragma unroll
        for (int stride = 8; stride >= 1; stride >>= 1)
#pragma unroll
            for (int i = 0; i < stride; i++) v[i] = add2(v[i], v[i + stride]);
        float lo, hi;
        upk(v[0], lo, hi);
        float s = lo + hi;
        s += __shfl_xor_sync(0xffffffffu, s, 16);
        s += __shfl_xor_sync(0xffffffffu, s, 8);
        s += __shfl_xor_sync(0xffffffffu, s, 4);
        s += __shfl_xor_sync(0xffffffffu, s, 2);
        s += __shfl_xor_sync(0xffffffffu, s, 1);

        if (lane == 0) {
            float y = fmaxf(s + pre_cur + myb2, 0.f);
            // clear sign bit: mathematically a no-op on ReLU output, and it IS the ready tag
            y = __uint_as_float(__float_as_uint(y) & 0x7FFFFFFFu);
            stvol_f32(&g_hs[(size_t)(t + 1) * DD + myrow], y);
        }
        __syncthreads();   // protect s_part reuse next iteration
    }
}

// ---------------- final tiny matvec: out[j] = h . Wf[j] + bf[j] ----------------
__global__ void final_kernel(const float* __restrict__ Wf,
                             const float* __restrict__ bf,
                             float* __restrict__ out)
{
    const int wid = threadIdx.x >> 5;   // 4 warps, one per output row
    const int lane = threadIdx.x & 31;
    const float* h = g_hs + (size_t)TT * DD;
    const float* w = Wf + (size_t)wid * DD;
    float s = 0.f;
#pragma unroll
    for (int i = 0; i < 16; i++) {
        int k = i * 128 + lane * 4;
        float4 hv = *(const float4*)(h + k);
        float4 wv = *(const float4*)(w + k);
        s += hv.x * wv.x + hv.y * wv.y + hv.z * wv.z + hv.w * wv.w;
    }
    for (int off = 16; off; off >>= 1) s += __shfl_xor_sync(0xffffffffu, s, off);
    if (lane == 0) out[wid] = s + bf[wid];
}

// ---------------- launch ----------------
extern "C" void kernel_launch(void* const* d_in, const int* in_sizes, int n_in,
                              void* d_out, int out_size)
{
    const float* x  = (const float*)d_in[0];
    const float* h0 = (const float*)d_in[1];
    const float* W1 = (const float*)d_in[2];
    const float* b1 = (const float*)d_in[3];
    const float* W2 = (const float*)d_in[4];
    const float* b2 = (const float*)d_in[5];
    const float* Wf = (const float*)d_in[6];
    const float* bf = (const float*)d_in[7];
    float* out = (float*)d_out;

    cudaFuncSetAttribute(scan_kernel, cudaFuncAttributeMaxDynamicSharedMemorySize,
                         ROWS * NTH * (int)sizeof(ull));

    poison_kernel<<<2048, 256>>>();
    gemm_kernel<<<dim3(DD / BN, TT / BM), 256>>>(x, W1, b1);
    scan_kernel<<<NCTA, NTH, ROWS * NTH * sizeof(ull)>>>(h0, W2, b2);
    final_kernel<<<1, 128>>>(Wf, bf, out);
}

// round 9
// speedup vs baseline: 1.6657x; 1.1731x over previous
#include <cuda_runtime.h>
#include <cstdint>

#define TT 8192
#define DD 2048

typedef unsigned long long ull;

// ---------------- device scratch (no allocations allowed) ----------------
__device__ float g_pre[(size_t)TT * DD];        // 64 MB: pre = x @ W1^T + b1
__device__ float g_hs[(size_t)(TT + 1) * DD];   // 64 MB: h per step; sign bit = not-ready

// ---------------- packed f32x2 helpers ----------------
__device__ __forceinline__ ull pk(float lo, float hi) {
    ull r;
    asm("mov.b64 %0, {%1, %2};" : "=l"(r) : "f"(lo), "f"(hi));
    return r;
}
__device__ __forceinline__ void upk(ull v, float& lo, float& hi) {
    asm("mov.b64 {%0, %1}, %2;" : "=f"(lo), "=f"(hi) : "l"(v));
}
__device__ __forceinline__ void fma2(ull& d, ull a, ull b) {
    asm("fma.rn.f32x2 %0, %1, %2, %0;" : "+l"(d) : "l"(a), "l"(b));
}

// ---------------- volatile ld/st (morally strong, guaranteed fresh+live) ----------
__device__ __forceinline__ uint4 ldvol_v4(const float* p) {
    uint4 v;
    asm volatile("ld.volatile.global.v4.u32 {%0,%1,%2,%3}, [%4];"
                 : "=r"(v.x), "=r"(v.y), "=r"(v.z), "=r"(v.w) : "l"(p));
    return v;
}
__device__ __forceinline__ void stvol_f32(float* p, float v) {
    asm volatile("st.volatile.global.f32 [%0], %1;" :: "l"(p), "f"(v));
}

// ---------------- poison kernel: set sign bits (= not ready) everywhere ----------
__global__ void poison_kernel() {
    uint4 p = make_uint4(0xFFFFFFFFu, 0xFFFFFFFFu, 0xFFFFFFFFu, 0xFFFFFFFFu);
    size_t n = (size_t)(TT + 1) * DD / 4;
    uint4* dst = (uint4*)g_hs;
    for (size_t i = (size_t)blockIdx.x * blockDim.x + threadIdx.x; i < n;
         i += (size_t)gridDim.x * blockDim.x)
        dst[i] = p;
}

// ---------------- GEMM: g_pre[t][n] = sum_k x[t][k] * W1[n][k] + b1[n] ----------------
#define BM 128
#define BN 128
#define BK 16
#define LDP 132

__global__ __launch_bounds__(256, 2) void gemm_kernel(
    const float* __restrict__ A,      // x  (TT x DD)
    const float* __restrict__ B,      // W1 (DD x DD), computing A @ B^T
    const float* __restrict__ bias)   // b1
{
    __shared__ __align__(16) float As[BK][LDP];
    __shared__ __align__(16) float Bs[BK][LDP];

    const int tid = threadIdx.x;
    const int m0 = blockIdx.y * BM;
    const int n0 = blockIdx.x * BN;
    const int tx = tid & 15;
    const int ty = tid >> 4;

    ull acc[8][4];
#pragma unroll
    for (int r = 0; r < 8; r++)
#pragma unroll
        for (int c = 0; c < 4; c++) acc[r][c] = 0ull;

    for (int k0 = 0; k0 < DD; k0 += BK) {
#pragma unroll
        for (int i = 0; i < 2; i++) {
            int id = tid + i * 256;
            int r = id >> 2;
            int c = (id & 3) * 4;
            float4 va = *(const float4*)(A + (size_t)(m0 + r) * DD + k0 + c);
            As[c + 0][r] = va.x; As[c + 1][r] = va.y;
            As[c + 2][r] = va.z; As[c + 3][r] = va.w;
            float4 vb = *(const float4*)(B + (size_t)(n0 + r) * DD + k0 + c);
            Bs[c + 0][r] = vb.x; Bs[c + 1][r] = vb.y;
            Bs[c + 2][r] = vb.z; Bs[c + 3][r] = vb.w;
        }
        __syncthreads();

#pragma unroll
        for (int k = 0; k < BK; k++) {
            float4 a0 = *(const float4*)&As[k][ty * 8];
            float4 a1 = *(const float4*)&As[k][ty * 8 + 4];
            ulonglong2 bq0 = *(const ulonglong2*)&Bs[k][tx * 8];
            ulonglong2 bq1 = *(const ulonglong2*)&Bs[k][tx * 8 + 4];
            ull bp0 = bq0.x, bp1 = bq0.y, bp2 = bq1.x, bp3 = bq1.y;
            float ar[8] = {a0.x, a0.y, a0.z, a0.w, a1.x, a1.y, a1.z, a1.w};
#pragma unroll
            for (int r = 0; r < 8; r++) {
                ull ad = pk(ar[r], ar[r]);
                fma2(acc[r][0], ad, bp0);
                fma2(acc[r][1], ad, bp1);
                fma2(acc[r][2], ad, bp2);
                fma2(acc[r][3], ad, bp3);
            }
        }
        __syncthreads();
    }

#pragma unroll
    for (int c = 0; c < 4; c++) {
        int n = n0 + tx * 8 + c * 2;
        float blo = bias[n], bhi = bias[n + 1];
#pragma unroll
        for (int r = 0; r < 8; r++) {
            float lo, hi;
            upk(acc[r][c], lo, hi);
            int m = m0 + ty * 8 + r;
            *(float2*)(g_pre + (size_t)m * DD + n) = make_float2(lo + blo, hi + bhi);
        }
    }
}

// ---------------- persistent scan kernel (sign-bit dataflow sync) ------------------
#define NCTA 128
#define NTH  512
#define ROWS 16   // DD / NCTA rows per CTA; warp w reduces row w
// thread t owns k-chunk [4t, 4t+4)

struct StepCtx {
    ull w2r0[ROWS], w2r1[ROWS];
    int tid, lane, wid, myrow;
    float myb2;
};

__device__ __forceinline__ void step_body(
    const StepCtx& c, float* s_buf,           // this step's partial buffer (ROWS*NTH floats)
    float h0v, float h1v, float h2v, float h3v,
    float pre_cur, float* hstore)             // &g_hs[(t+1)*DD + myrow]
{
    ull h01 = pk(h0v, h1v);
    ull h23 = pk(h2v, h3v);
#pragma unroll
    for (int j = 0; j < ROWS; j++) {
        ull acc = 0ull;
        fma2(acc, c.w2r0[j], h01);
        fma2(acc, c.w2r1[j], h23);
        float lo, hi;
        upk(acc, lo, hi);
        s_buf[j * NTH + c.tid] = lo + hi;     // scalar partial: halves smem traffic
    }
    __syncthreads();

    // warp `wid` reduces row `wid`: 512 scalars via 4 x LDS.128 per lane
    const float* rowp = s_buf + c.wid * NTH;
    float s = 0.f;
#pragma unroll
    for (int i = 0; i < 4; i++) {
        float4 v = *(const float4*)(rowp + i * 128 + c.lane * 4);
        s += (v.x + v.y) + (v.z + v.w);
    }
    s += __shfl_xor_sync(0xffffffffu, s, 16);
    s += __shfl_xor_sync(0xffffffffu, s, 8);
    s += __shfl_xor_sync(0xffffffffu, s, 4);
    s += __shfl_xor_sync(0xffffffffu, s, 2);
    s += __shfl_xor_sync(0xffffffffu, s, 1);

    if (c.lane == 0) {
        float y = fmaxf(s + pre_cur + c.myb2, 0.f);
        // clear sign bit: no-op on ReLU output, and it IS the ready tag
        y = __uint_as_float(__float_as_uint(y) & 0x7FFFFFFFu);
        stvol_f32(hstore, y);
    }
    // no trailing barrier: double-buffered s_part + per-step BAR + dataflow poll
    // make a >1-step skew (and thus buffer reuse hazard) impossible.
}

__global__ __launch_bounds__(NTH, 1) void scan_kernel(
    const float* __restrict__ h0,
    const float* __restrict__ W2,
    const float* __restrict__ b2)
{
    extern __shared__ float s_part[];   // [2][ROWS*NTH] floats = 64 KB
    StepCtx c;
    c.tid  = threadIdx.x;
    c.lane = c.tid & 31;
    c.wid  = c.tid >> 5;
    const int blk = blockIdx.x;
    const int k0  = c.tid * 4;

    // register-resident W2 slab: rows [blk*16, blk*16+16), cols [k0, k0+4)
#pragma unroll
    for (int j = 0; j < ROWS; j++) {
        float4 w = *(const float4*)(W2 + (size_t)(blk * ROWS + j) * DD + k0);
        c.w2r0[j] = pk(w.x, w.y);
        c.w2r1[j] = pk(w.z, w.w);
    }
    c.myrow = blk * ROWS + c.wid;
    c.myb2  = b2[c.myrow];
    float pre_next = __ldg(&g_pre[c.myrow]);

    // ---- step 0 (h0 is input; no poll, may be negative) ----
    {
        float4 hv = *(const float4*)(h0 + k0);
        float pre_cur = pre_next;
        pre_next = __ldg(&g_pre[(size_t)1 * DD + c.myrow]);
        step_body(c, s_part, hv.x, hv.y, hv.z, hv.w, pre_cur,
                  &g_hs[(size_t)1 * DD + c.myrow]);
    }

    // ---- steps 1..TT-1 ----
    for (int t = 1; t < TT; t++) {
        const float* src = g_hs + (size_t)t * DD + k0;
        uint4 a = ldvol_v4(src);
        while (((a.x | a.y | a.z | a.w) & 0x80000000u) != 0u) {
            __nanosleep(40);            // backoff: cut spin-generated L2 traffic
            a = ldvol_v4(src);
        }
        float pre_cur = pre_next;
        if (t + 1 < TT) pre_next = __ldg(&g_pre[(size_t)(t + 1) * DD + c.myrow]);

        step_body(c, s_part + (t & 1) * (ROWS * NTH),
                  __uint_as_float(a.x), __uint_as_float(a.y),
                  __uint_as_float(a.z), __uint_as_float(a.w),
                  pre_cur, &g_hs[(size_t)(t + 1) * DD + c.myrow]);
    }
}

// ---------------- final tiny matvec: out[j] = h . Wf[j] + bf[j] ----------------
__global__ void final_kernel(const float* __restrict__ Wf,
                             const float* __restrict__ bf,
                             float* __restrict__ out)
{
    const int wid = threadIdx.x >> 5;   // 4 warps, one per output row
    const int lane = threadIdx.x & 31;
    const float* h = g_hs + (size_t)TT * DD;
    const float* w = Wf + (size_t)wid * DD;
    float s = 0.f;
#pragma unroll
    for (int i = 0; i < 16; i++) {
        int k = i * 128 + lane * 4;
        float4 hv = *(const float4*)(h + k);
        float4 wv = *(const float4*)(w + k);
        s += hv.x * wv.x + hv.y * wv.y + hv.z * wv.z + hv.w * wv.w;
    }
    for (int off = 16; off; off >>= 1) s += __shfl_xor_sync(0xffffffffu, s, off);
    if (lane == 0) out[wid] = s + bf[wid];
}

// ---------------- launch ----------------
extern "C" void kernel_launch(void* const* d_in, const int* in_sizes, int n_in,
                              void* d_out, int out_size)
{
    const float* x  = (const float*)d_in[0];
    const float* h0 = (const float*)d_in[1];
    const float* W1 = (const float*)d_in[2];
    const float* b1 = (const float*)d_in[3];
    const float* W2 = (const float*)d_in[4];
    const float* b2 = (const float*)d_in[5];
    const float* Wf = (const float*)d_in[6];
    const float* bf = (const float*)d_in[7];
    float* out = (float*)d_out;

    cudaFuncSetAttribute(scan_kernel, cudaFuncAttributeMaxDynamicSharedMemorySize,
                         2 * ROWS * NTH * (int)sizeof(float));

    poison_kernel<<<2048, 256>>>();
    gemm_kernel<<<dim3(DD / BN, TT / BM), 256>>>(x, W1, b1);
    scan_kernel<<<NCTA, NTH, 2 * ROWS * NTH * sizeof(float)>>>(h0, W2, b2);
    final_kernel<<<1, 128>>>(Wf, bf, out);
}